// round 6
// baseline (speedup 1.0000x reference)
#include <cuda_runtime.h>
#include <cstdint>

// VariationalLinear: out[1024,4096] = x @ (mu + eps_w*sigma)^T + (b_mu + eps_b*b_sigma)
// compute_103-safe path: mma.sync tf32 (m16n8k8) + cp.async. tcgen05 is rejected by
// this harness's virtual arch (compute_103), so HMMA it is.
// Kernel 1: round x to tf32 (rna) into scratch.  Kernel 2: fused GEMM.
// GEMM tiling: BM=256, BN=128, BK=32; 8 warps (4x2), warp tile 64x64; grid (4,32).

static constexpr int MDIM = 1024, NDIM = 4096, KDIM = 4096;
static constexpr int BM = 256, BN = 128, BK = 32;
static constexpr int KCH = KDIM / BK;        // 128
static constexpr int THREADS = 256;
static constexpr int ROWB = 144;             // 32 floats + 16B pad: conflict-free, no swizzle
static constexpr int ASTG = BM * ROWB;       // 36864
static constexpr int BSTG = BN * ROWB;       // 18432
static constexpr int OFF_A = 512;            // [0,512) = fused bias
static constexpr int OFF_B = OFF_A + 2 * ASTG;
static constexpr int SMEM_TOTAL = OFF_B + 2 * BSTG;   // 111104

__device__ float g_xr[MDIM * KDIM];          // tf32-rounded x (scratch, 16.8 MB)

__device__ __forceinline__ float tf32r(float f) {    // round-to-NEAREST tf32
    uint32_t u;
    asm("cvt.rna.tf32.f32 %0, %1;" : "=r"(u) : "f"(f));
    return __uint_as_float(u);
}
__device__ __forceinline__ uint32_t smem_u32(const void* p) {
    uint32_t a;
    asm("{ .reg .u64 t; cvta.to.shared.u64 t, %1; cvt.u32.u64 %0, t; }" : "=r"(a) : "l"(p));
    return a;
}
__device__ __forceinline__ void cp16(uint32_t dst, const void* src) {
    asm volatile("cp.async.cg.shared.global [%0], [%1], 16;" :: "r"(dst), "l"(src));
}
#define CP_COMMIT() asm volatile("cp.async.commit_group;" ::: "memory")
#define CP_WAIT0()  asm volatile("cp.async.wait_group 0;" ::: "memory")

#define MMA8(ac, a, b) asm volatile( \
    "mma.sync.aligned.m16n8k8.row.col.f32.tf32.tf32.f32 " \
    "{%0,%1,%2,%3}, {%4,%5,%6,%7}, {%8,%9}, {%0,%1,%2,%3};" \
    : "+f"((ac)[0]), "+f"((ac)[1]), "+f"((ac)[2]), "+f"((ac)[3]) \
    : "r"((a)[0]), "r"((a)[1]), "r"((a)[2]), "r"((a)[3]), "r"((b)[0]), "r"((b)[1]))

// ---------------- Kernel 1: x -> tf32(rna) scratch ----------------
__global__ void __launch_bounds__(256) prep_x(const float* __restrict__ x) {
    int i = blockIdx.x * 256 + threadIdx.x;          // one float4 per thread
    float4 v = ((const float4*)x)[i];
    v.x = tf32r(v.x); v.y = tf32r(v.y); v.z = tf32r(v.z); v.w = tf32r(v.w);
    ((float4*)g_xr)[i] = v;
}

// ---------------- Kernel 2: fused tf32 GEMM ----------------
__global__ void __launch_bounds__(THREADS, 1)
vlin_gemm(const float* __restrict__ wmu, const float* __restrict__ wsig,
          const float* __restrict__ ew,  const float* __restrict__ bmu,
          const float* __restrict__ bsig, const float* __restrict__ eb,
          float* __restrict__ out) {
    extern __shared__ char smem[];
    const uint32_t sb = smem_u32(smem);
    const int tid = threadIdx.x, wid = tid >> 5, lid = tid & 31;
    const int wm = wid >> 1, wn = wid & 1;           // warp grid 4(m) x 2(n)
    const int g = lid >> 2, tg = lid & 3;            // mma lane mapping
    const int m0 = blockIdx.x * BM, n0 = blockIdx.y * BN;
    const int c4 = tid & 7, r0 = tid >> 3;           // loader mapping: 8 cols x 32 rows

    if (tid < BN)
        ((float*)smem)[tid] = fmaf(eb[n0 + tid], bsig[n0 + tid], bmu[n0 + tid]);

    // per-thread gmem slices
    const float* xsrc = g_xr + (size_t)(m0 + r0) * KDIM + c4 * 4;
    const size_t wrow = (size_t)(n0 + r0) * KDIM + c4 * 4;
    const uint32_t a_dst = sb + OFF_A + r0 * ROWB + c4 * 16;
    char* b_dst = smem + OFF_B + r0 * ROWB + c4 * 16;

    // fragment smem offsets (within a stage)
    int aoff[8], boff[8];
    #pragma unroll
    for (int mt = 0; mt < 4; mt++) {
        aoff[2 * mt]     = (wm * 64 + mt * 16 + g) * ROWB + tg * 4;
        aoff[2 * mt + 1] = (wm * 64 + mt * 16 + g + 8) * ROWB + tg * 4;
    }
    #pragma unroll
    for (int nt = 0; nt < 8; nt++) boff[nt] = (wn * 64 + nt * 8 + g) * ROWB + tg * 4;

    float acc[4][8][4];
    #pragma unroll
    for (int mt = 0; mt < 4; mt++)
        #pragma unroll
        for (int nt = 0; nt < 8; nt++)
            #pragma unroll
            for (int q = 0; q < 4; q++) acc[mt][nt][q] = 0.f;

    // ---- prologue: chunk 0 -> stage 0 ----
    #pragma unroll
    for (int p = 0; p < 8; p++) cp16(a_dst + p * 32 * ROWB, xsrc + (size_t)p * 32 * KDIM);
    CP_COMMIT();
    #pragma unroll
    for (int p = 0; p < 4; p++) {
        size_t gi = wrow + (size_t)p * 32 * KDIM;
        float4 m4 = *(const float4*)(wmu + gi);
        float4 s4 = *(const float4*)(wsig + gi);
        float4 e4 = *(const float4*)(ew + gi);
        float4 w;
        w.x = tf32r(fmaf(e4.x, s4.x, m4.x));
        w.y = tf32r(fmaf(e4.y, s4.y, m4.y));
        w.z = tf32r(fmaf(e4.z, s4.z, m4.z));
        w.w = tf32r(fmaf(e4.w, s4.w, m4.w));
        *(float4*)(b_dst + p * 32 * ROWB) = w;
    }

    // ---- main loop: double-buffered ----
    #pragma unroll 1
    for (int i = 0; i < KCH; i++) {
        const int s = i & 1;
        CP_WAIT0();
        __syncthreads();     // stage s fully loaded; stage s^1 fully consumed

        float4 m4[4], s4[4], e4[4];
        if (i < KCH - 1) {   // prefetch chunk i+1 -> stage s^1
            const float* xs = xsrc + (i + 1) * BK;
            const uint32_t ad = a_dst + (s ^ 1) * ASTG;
            #pragma unroll
            for (int p = 0; p < 8; p++) cp16(ad + p * 32 * ROWB, xs + (size_t)p * 32 * KDIM);
            CP_COMMIT();
            #pragma unroll
            for (int p = 0; p < 4; p++) {
                size_t gi = wrow + (size_t)(i + 1) * BK + (size_t)p * 32 * KDIM;
                m4[p] = *(const float4*)(wmu + gi);
                s4[p] = *(const float4*)(wsig + gi);
                e4[p] = *(const float4*)(ew + gi);
            }
        }

        // compute on stage s
        const char* aS = smem + OFF_A + s * ASTG;
        const char* bS = smem + OFF_B + s * BSTG;
        #pragma unroll
        for (int ks = 0; ks < 4; ks++) {
            uint32_t a[4][4], b[8][2];
            #pragma unroll
            for (int mt = 0; mt < 4; mt++) {
                a[mt][0] = *(const uint32_t*)(aS + aoff[2 * mt]     + ks * 32);
                a[mt][1] = *(const uint32_t*)(aS + aoff[2 * mt + 1] + ks * 32);
                a[mt][2] = *(const uint32_t*)(aS + aoff[2 * mt]     + ks * 32 + 16);
                a[mt][3] = *(const uint32_t*)(aS + aoff[2 * mt + 1] + ks * 32 + 16);
            }
            #pragma unroll
            for (int nt = 0; nt < 8; nt++) {
                b[nt][0] = *(const uint32_t*)(bS + boff[nt] + ks * 32);
                b[nt][1] = *(const uint32_t*)(bS + boff[nt] + ks * 32 + 16);
            }
            #pragma unroll
            for (int mt = 0; mt < 4; mt++)
                #pragma unroll
                for (int nt = 0; nt < 8; nt++)
                    MMA8(acc[mt][nt], a[mt], b[nt]);
        }

        if (i < KCH - 1) {   // fuse + store weights for chunk i+1
            char* bd = b_dst + (s ^ 1) * BSTG;
            #pragma unroll
            for (int p = 0; p < 4; p++) {
                float4 w;
                w.x = tf32r(fmaf(e4[p].x, s4[p].x, m4[p].x));
                w.y = tf32r(fmaf(e4[p].y, s4[p].y, m4[p].y));
                w.z = tf32r(fmaf(e4[p].z, s4[p].z, m4[p].z));
                w.w = tf32r(fmaf(e4[p].w, s4[p].w, m4[p].w));
                *(float4*)(bd + p * 32 * ROWB) = w;
            }
        }
    }

    // ---- epilogue: accums + bias -> GMEM ----
    const float* bias_s = (const float*)smem;
    #pragma unroll
    for (int mt = 0; mt < 4; mt++) {
        #pragma unroll
        for (int nt = 0; nt < 8; nt++) {
            const int bc = wn * 64 + nt * 8 + 2 * tg;
            const int R0 = m0 + wm * 64 + mt * 16 + g;
            const int C  = n0 + bc;
            float2 v0 = { acc[mt][nt][0] + bias_s[bc], acc[mt][nt][1] + bias_s[bc + 1] };
            float2 v1 = { acc[mt][nt][2] + bias_s[bc], acc[mt][nt][3] + bias_s[bc + 1] };
            *(float2*)(out + (size_t)R0 * NDIM + C) = v0;
            *(float2*)(out + (size_t)(R0 + 8) * NDIM + C) = v1;
        }
    }
}

extern "C" void kernel_launch(void* const* d_in, const int* in_sizes, int n_in,
                              void* d_out, int out_size) {
    (void)in_sizes; (void)n_in; (void)out_size;
    cudaFuncSetAttribute(vlin_gemm, cudaFuncAttributeMaxDynamicSharedMemorySize, SMEM_TOTAL);

    // inputs: x, weight_mu, weight_sigma, bias_mu, bias_sigma, eps_w, eps_b
    prep_x<<<(MDIM * KDIM / 4) / 256, 256>>>((const float*)d_in[0]);
    dim3 grid(MDIM / BM, NDIM / BN);   // (4, 32)
    vlin_gemm<<<grid, THREADS, SMEM_TOTAL>>>(
        (const float*)d_in[1], (const float*)d_in[2], (const float*)d_in[5],
        (const float*)d_in[3], (const float*)d_in[4], (const float*)d_in[6],
        (float*)d_out);
}

// round 7
// speedup vs baseline: 1.2819x; 1.2819x over previous
#include <cuda_runtime.h>
#include <cuda_fp16.h>
#include <cstdint>

// VariationalLinear: out[1024,4096] = x @ (mu + eps_w*sigma)^T + (b_mu + eps_b*b_sigma)
// compute_103-safe legacy tensor path. fp16 HMMA m16n8k16 (same 10-bit mantissa as
// tf32, 2x K per instruction), fp32 accumulate.
// Kernel 1: x -> fp16(rn) scratch. Kernel 2: fused GEMM.
// BM=256, BN=128, BK=32, 512 threads (16 warps, 4x4 grid, 64x32 warp tiles), grid (4,32).

static constexpr int MDIM = 1024, NDIM = 4096, KDIM = 4096;
static constexpr int BM = 256, BN = 128, BK = 32;
static constexpr int KCH = KDIM / BK;      // 128
static constexpr int THREADS = 512;
static constexpr int ROWB = 80;            // 32 halves (64B) + 16B pad: conflict-free frags
static constexpr int ASTG = BM * ROWB;     // 20480
static constexpr int BSTG = BN * ROWB;     // 10240
static constexpr int OFF_A = 512;          // [0,512) fused bias
static constexpr int OFF_B = OFF_A + 2 * ASTG;        // 41472
static constexpr int SMEM_TOTAL = OFF_B + 2 * BSTG;   // 61952

__device__ __align__(16) __half g_xh[MDIM * KDIM];    // fp16-rounded x (8.4 MB)

__device__ __forceinline__ uint32_t smem_u32(const void* p) {
    uint32_t a;
    asm("{ .reg .u64 t; cvta.to.shared.u64 t, %1; cvt.u32.u64 %0, t; }" : "=r"(a) : "l"(p));
    return a;
}
__device__ __forceinline__ void cp16(uint32_t dst, const void* src) {
    asm volatile("cp.async.cg.shared.global [%0], [%1], 16;" :: "r"(dst), "l"(src));
}
#define CP_COMMIT() asm volatile("cp.async.commit_group;" ::: "memory")
#define CP_WAIT0()  asm volatile("cp.async.wait_group 0;" ::: "memory")

#define MMA16(ac, a, b) asm volatile( \
    "mma.sync.aligned.m16n8k16.row.col.f32.f16.f16.f32 " \
    "{%0,%1,%2,%3}, {%4,%5,%6,%7}, {%8,%9}, {%0,%1,%2,%3};" \
    : "+f"((ac)[0]), "+f"((ac)[1]), "+f"((ac)[2]), "+f"((ac)[3]) \
    : "r"((a)[0]), "r"((a)[1]), "r"((a)[2]), "r"((a)[3]), "r"((b)[0]), "r"((b)[1]))

// ---------------- Kernel 1: x -> fp16 scratch ----------------
__global__ void __launch_bounds__(256) prep_x(const float* __restrict__ x) {
    int i = blockIdx.x * 256 + threadIdx.x;          // 8 floats per thread
    const float4* src = (const float4*)x;
    float4 v0 = src[2 * i], v1 = src[2 * i + 1];
    __half2 h[4];
    h[0] = __floats2half2_rn(v0.x, v0.y);
    h[1] = __floats2half2_rn(v0.z, v0.w);
    h[2] = __floats2half2_rn(v1.x, v1.y);
    h[3] = __floats2half2_rn(v1.z, v1.w);
    ((uint4*)g_xh)[i] = *(uint4*)h;
}

// ---------------- Kernel 2: fused fp16 GEMM ----------------
__global__ void __launch_bounds__(THREADS, 1)
vlin_gemm(const float* __restrict__ wmu, const float* __restrict__ wsig,
          const float* __restrict__ ew,  const float* __restrict__ bmu,
          const float* __restrict__ bsig, const float* __restrict__ eb,
          float* __restrict__ out) {
    extern __shared__ char smem[];
    const uint32_t sb = smem_u32(smem);
    const int tid = threadIdx.x, wid = tid >> 5, lid = tid & 31;
    const int wm = wid >> 2, wn = wid & 3;           // 4(m) x 4(n) warp grid
    const int g = lid >> 2, tg = lid & 3;            // mma lane mapping
    const int m0 = blockIdx.x * BM, n0 = blockIdx.y * BN;

    if (tid < BN)
        ((float*)smem)[tid] = fmaf(eb[n0 + tid], bsig[n0 + tid], bmu[n0 + tid]);

    // loader mapping: A = 2 cp16/thread (rows rL, rL+128); W = 8 floats/thread (row rL)
    const int cL = tid & 3, rL = tid >> 2;           // 4 x 16B segs per 64B row; 128 rows
    const __half* xsrc = g_xh + (size_t)(m0 + rL) * KDIM + cL * 8;
    const size_t wrow = (size_t)(n0 + rL) * KDIM + cL * 8;
    const uint32_t aDst = sb + OFF_A + rL * ROWB + cL * 16;
    char* bDst = smem + OFF_B + rL * ROWB + cL * 16;

    // fragment base offsets within a stage (bytes)
    uint32_t aoff[4], boff[4];
    #pragma unroll
    for (int mt = 0; mt < 4; mt++) aoff[mt] = (wm * 64 + mt * 16 + g) * ROWB + tg * 4;
    #pragma unroll
    for (int nt = 0; nt < 4; nt++) boff[nt] = (wn * 32 + nt * 8 + g) * ROWB + tg * 4;

    float acc[4][4][4];
    #pragma unroll
    for (int mt = 0; mt < 4; mt++)
        #pragma unroll
        for (int nt = 0; nt < 4; nt++)
            #pragma unroll
            for (int q = 0; q < 4; q++) acc[mt][nt][q] = 0.f;

    // ---- prologue: chunk 0 -> stage 0 ----
    cp16(aDst, xsrc);
    cp16(aDst + 128 * ROWB, xsrc + (size_t)128 * KDIM);
    CP_COMMIT();
    {
        float4 m4[2], s4[2], e4[2];
        #pragma unroll
        for (int p = 0; p < 2; p++) {
            m4[p] = *(const float4*)(wmu + wrow + p * 4);
            s4[p] = *(const float4*)(wsig + wrow + p * 4);
            e4[p] = *(const float4*)(ew + wrow + p * 4);
        }
        __half2 h[4];
        #pragma unroll
        for (int p = 0; p < 2; p++) {
            h[2 * p]     = __floats2half2_rn(fmaf(e4[p].x, s4[p].x, m4[p].x),
                                             fmaf(e4[p].y, s4[p].y, m4[p].y));
            h[2 * p + 1] = __floats2half2_rn(fmaf(e4[p].z, s4[p].z, m4[p].z),
                                             fmaf(e4[p].w, s4[p].w, m4[p].w));
        }
        *(uint4*)bDst = *(uint4*)h;
    }

    // ---- main loop: double-buffered ----
    #pragma unroll 1
    for (int i = 0; i < KCH; i++) {
        const int s = i & 1;
        CP_WAIT0();
        __syncthreads();     // stage s ready; stage s^1 consumed

        float4 m4[2], s4[2], e4[2];
        if (i < KCH - 1) {   // prefetch chunk i+1 -> stage s^1
            const __half* xs = xsrc + (i + 1) * BK;
            const uint32_t ad = aDst + (s ^ 1) * ASTG;
            cp16(ad, xs);
            cp16(ad + 128 * ROWB, xs + (size_t)128 * KDIM);
            CP_COMMIT();
            const size_t wb = wrow + (size_t)(i + 1) * BK;
            #pragma unroll
            for (int p = 0; p < 2; p++) {
                m4[p] = *(const float4*)(wmu + wb + p * 4);
                s4[p] = *(const float4*)(wsig + wb + p * 4);
                e4[p] = *(const float4*)(ew + wb + p * 4);
            }
        }

        // compute on stage s: 2 ksteps of k=16
        const char* aS = smem + OFF_A + s * ASTG;
        const char* bS = smem + OFF_B + s * BSTG;
        #pragma unroll
        for (int ks = 0; ks < 2; ks++) {
            uint32_t a[4][4], b[4][2];
            #pragma unroll
            for (int mt = 0; mt < 4; mt++) {
                a[mt][0] = *(const uint32_t*)(aS + aoff[mt] + ks * 32);
                a[mt][1] = *(const uint32_t*)(aS + aoff[mt] + ks * 32 + 8 * ROWB);
                a[mt][2] = *(const uint32_t*)(aS + aoff[mt] + ks * 32 + 16);
                a[mt][3] = *(const uint32_t*)(aS + aoff[mt] + ks * 32 + 8 * ROWB + 16);
            }
            #pragma unroll
            for (int nt = 0; nt < 4; nt++) {
                b[nt][0] = *(const uint32_t*)(bS + boff[nt] + ks * 32);
                b[nt][1] = *(const uint32_t*)(bS + boff[nt] + ks * 32 + 16);
            }
            #pragma unroll
            for (int mt = 0; mt < 4; mt++)
                #pragma unroll
                for (int nt = 0; nt < 4; nt++)
                    MMA16(acc[mt][nt], a[mt], b[nt]);
        }

        if (i < KCH - 1) {   // fuse + store weights for chunk i+1
            __half2 h[4];
            #pragma unroll
            for (int p = 0; p < 2; p++) {
                h[2 * p]     = __floats2half2_rn(fmaf(e4[p].x, s4[p].x, m4[p].x),
                                                 fmaf(e4[p].y, s4[p].y, m4[p].y));
                h[2 * p + 1] = __floats2half2_rn(fmaf(e4[p].z, s4[p].z, m4[p].z),
                                                 fmaf(e4[p].w, s4[p].w, m4[p].w));
            }
            *(uint4*)(bDst + (s ^ 1) * BSTG) = *(uint4*)h;
        }
    }

    // ---- epilogue: acc + bias -> GMEM ----
    const float* bias_s = (const float*)smem;
    #pragma unroll
    for (int mt = 0; mt < 4; mt++) {
        #pragma unroll
        for (int nt = 0; nt < 4; nt++) {
            const int bc = wn * 32 + nt * 8 + 2 * tg;
            const int R0 = m0 + wm * 64 + mt * 16 + g;
            float2 v0 = { acc[mt][nt][0] + bias_s[bc], acc[mt][nt][1] + bias_s[bc + 1] };
            float2 v1 = { acc[mt][nt][2] + bias_s[bc], acc[mt][nt][3] + bias_s[bc + 1] };
            *(float2*)(out + (size_t)R0 * NDIM + n0 + bc) = v0;
            *(float2*)(out + (size_t)(R0 + 8) * NDIM + n0 + bc) = v1;
        }
    }
}

extern "C" void kernel_launch(void* const* d_in, const int* in_sizes, int n_in,
                              void* d_out, int out_size) {
    (void)in_sizes; (void)n_in; (void)out_size;
    cudaFuncSetAttribute(vlin_gemm, cudaFuncAttributeMaxDynamicSharedMemorySize, SMEM_TOTAL);

    // inputs: x, weight_mu, weight_sigma, bias_mu, bias_sigma, eps_w, eps_b
    prep_x<<<(MDIM * KDIM / 8) / 256, 256>>>((const float*)d_in[0]);
    dim3 grid(MDIM / BM, NDIM / BN);   // (4, 32)
    vlin_gemm<<<grid, THREADS, SMEM_TOTAL>>>(
        (const float*)d_in[1], (const float*)d_in[2], (const float*)d_in[5],
        (const float*)d_in[3], (const float*)d_in[4], (const float*)d_in[6],
        (float*)d_out);
}

// round 8
// speedup vs baseline: 1.3169x; 1.0273x over previous
#include <cuda_runtime.h>
#include <cuda_fp16.h>
#include <cstdint>

// VariationalLinear: out[1024,4096] = x @ (mu + eps_w*sigma)^T + (b_mu + eps_b*b_sigma)
// R8: split fusion out of GEMM.
//   prep_x: x -> fp16 scratch (8.4 MB)
//   prep_w: mu + eps*sigma -> fp16 scratch (33.5 MB)
//   vlin_gemm: pure fp16 HMMA GEMM, cp.async both operands, ldmatrix fragments.
// GEMM: BM=256, BN=128, BK=64, 512 thr (16 warps 4x4, 64x32 warp tiles), grid (4,32).

static constexpr int MDIM = 1024, NDIM = 4096, KDIM = 4096;
static constexpr int BM = 256, BN = 128, BK = 64;
static constexpr int KCH = KDIM / BK;       // 64
static constexpr int THREADS = 512;
static constexpr int ROWB = 144;            // 64 halves (128B) + 16B pad (bank-rotate 4)
static constexpr int ASTG = BM * ROWB;      // 36864
static constexpr int BSTG = BN * ROWB;      // 18432
static constexpr int OFF_A = 512;           // [0,512) fused bias
static constexpr int OFF_B = OFF_A + 2 * ASTG;        // 74240
static constexpr int SMEM_TOTAL = OFF_B + 2 * BSTG;   // 111104

__device__ __align__(16) __half g_xh[MDIM * KDIM];    // fp16 x (8.4 MB)
__device__ __align__(16) __half g_wh[NDIM * KDIM];    // fp16 fused W (33.5 MB)

__device__ __forceinline__ uint32_t smem_u32(const void* p) {
    uint32_t a;
    asm("{ .reg .u64 t; cvta.to.shared.u64 t, %1; cvt.u32.u64 %0, t; }" : "=r"(a) : "l"(p));
    return a;
}
__device__ __forceinline__ void cp16(uint32_t dst, const void* src) {
    asm volatile("cp.async.cg.shared.global [%0], [%1], 16;" :: "r"(dst), "l"(src));
}
#define CP_COMMIT() asm volatile("cp.async.commit_group;" ::: "memory")
#define CP_WAIT0()  asm volatile("cp.async.wait_group 0;" ::: "memory")

#define LDSM4(r, addr) asm volatile( \
    "ldmatrix.sync.aligned.m8n8.x4.shared.b16 {%0,%1,%2,%3}, [%4];" \
    : "=r"((r)[0]), "=r"((r)[1]), "=r"((r)[2]), "=r"((r)[3]) : "r"(addr))

#define MMA16(ac, a, b0, b1) asm volatile( \
    "mma.sync.aligned.m16n8k16.row.col.f32.f16.f16.f32 " \
    "{%0,%1,%2,%3}, {%4,%5,%6,%7}, {%8,%9}, {%0,%1,%2,%3};" \
    : "+f"((ac)[0]), "+f"((ac)[1]), "+f"((ac)[2]), "+f"((ac)[3]) \
    : "r"((a)[0]), "r"((a)[1]), "r"((a)[2]), "r"((a)[3]), "r"(b0), "r"(b1))

// ---------------- prep kernels ----------------
__global__ void __launch_bounds__(256) prep_x(const float* __restrict__ x) {
    int i = blockIdx.x * 256 + threadIdx.x;              // 8 floats / thread
    const float4* src = (const float4*)x;
    float4 v0 = src[2 * i], v1 = src[2 * i + 1];
    __half2 h[4];
    h[0] = __floats2half2_rn(v0.x, v0.y);  h[1] = __floats2half2_rn(v0.z, v0.w);
    h[2] = __floats2half2_rn(v1.x, v1.y);  h[3] = __floats2half2_rn(v1.z, v1.w);
    ((uint4*)g_xh)[i] = *(uint4*)h;
}
__global__ void __launch_bounds__(256) prep_w(const float* __restrict__ mu,
                                              const float* __restrict__ sg,
                                              const float* __restrict__ ep) {
    int i = blockIdx.x * 256 + threadIdx.x;              // 8 floats / thread
    const float4* M = (const float4*)mu;
    const float4* S = (const float4*)sg;
    const float4* E = (const float4*)ep;
    float4 m0 = M[2 * i], m1 = M[2 * i + 1];
    float4 s0 = S[2 * i], s1 = S[2 * i + 1];
    float4 e0 = E[2 * i], e1 = E[2 * i + 1];
    __half2 h[4];
    h[0] = __floats2half2_rn(fmaf(e0.x, s0.x, m0.x), fmaf(e0.y, s0.y, m0.y));
    h[1] = __floats2half2_rn(fmaf(e0.z, s0.z, m0.z), fmaf(e0.w, s0.w, m0.w));
    h[2] = __floats2half2_rn(fmaf(e1.x, s1.x, m1.x), fmaf(e1.y, s1.y, m1.y));
    h[3] = __floats2half2_rn(fmaf(e1.z, s1.z, m1.z), fmaf(e1.w, s1.w, m1.w));
    ((uint4*)g_wh)[i] = *(uint4*)h;
}

// ---------------- pure fp16 GEMM ----------------
__global__ void __launch_bounds__(THREADS, 1)
vlin_gemm(const float* __restrict__ bmu, const float* __restrict__ bsig,
          const float* __restrict__ eb,  float* __restrict__ out) {
    extern __shared__ char smem[];
    const uint32_t sb = smem_u32(smem);
    const int tid = threadIdx.x, wid = tid >> 5, lid = tid & 31;
    const int wm = wid >> 2, wn = wid & 3;               // 4(m) x 4(n) warps
    const int g = lid >> 2, tg = lid & 3;
    const int m0 = blockIdx.x * BM, n0 = blockIdx.y * BN;

    if (tid < BN)
        ((float*)smem)[tid] = fmaf(eb[n0 + tid], bsig[n0 + tid], bmu[n0 + tid]);

    // cp.async mapping: A 4x16B/thread (row tid>>1), B 2x16B/thread (row tid>>2)
    const int aR = tid >> 1, aC = (tid & 1) * 32;        // halves
    const int bR = tid >> 2, bC = (tid & 3) * 16;
    const __half* aSrc = g_xh + (size_t)(m0 + aR) * KDIM + aC;
    const __half* bSrc = g_wh + (size_t)(n0 + bR) * KDIM + bC;
    const uint32_t aDst = sb + OFF_A + aR * ROWB + aC * 2;
    const uint32_t bDst = sb + OFF_B + bR * ROWB + bC * 2;

    // ldmatrix lane addresses
    const int l15 = lid & 15, lHi = lid >> 4;
    const uint32_t aBase = sb + OFF_A + (wm * 64 + l15) * ROWB + lHi * 16;
    const uint32_t bBase = sb + OFF_B + (wn * 32 + l15) * ROWB + lHi * 16;

    float acc[4][4][4];
    #pragma unroll
    for (int mt = 0; mt < 4; mt++)
        #pragma unroll
        for (int nt = 0; nt < 4; nt++)
            #pragma unroll
            for (int q = 0; q < 4; q++) acc[mt][nt][q] = 0.f;

    // prologue: chunk 0 -> stage 0
    #pragma unroll
    for (int j = 0; j < 4; j++) cp16(aDst + j * 16, aSrc + j * 8);
    #pragma unroll
    for (int j = 0; j < 2; j++) cp16(bDst + j * 16, bSrc + j * 8);
    CP_COMMIT();

    #pragma unroll 1
    for (int i = 0; i < KCH; i++) {
        const int s = i & 1;
        CP_WAIT0();
        __syncthreads();                         // stage s ready; s^1 consumed

        if (i < KCH - 1) {                       // prefetch chunk i+1 -> stage s^1
            const __half* as = aSrc + (i + 1) * BK;
            const __half* bs = bSrc + (i + 1) * BK;
            const uint32_t ad = aDst + (s ^ 1) * ASTG;
            const uint32_t bd = bDst + (s ^ 1) * BSTG;
            #pragma unroll
            for (int j = 0; j < 4; j++) cp16(ad + j * 16, as + j * 8);
            #pragma unroll
            for (int j = 0; j < 2; j++) cp16(bd + j * 16, bs + j * 8);
            CP_COMMIT();
        }

        const uint32_t aS = aBase + s * ASTG;
        const uint32_t bS = bBase + s * BSTG;
        #pragma unroll
        for (int ks = 0; ks < 4; ks++) {         // 4 k-steps of 16
            uint32_t a[4][4], b[2][4];
            #pragma unroll
            for (int mt = 0; mt < 4; mt++) LDSM4(a[mt], aS + mt * 16 * ROWB + ks * 32);
            #pragma unroll
            for (int np = 0; np < 2; np++) LDSM4(b[np], bS + np * 16 * ROWB + ks * 32);
            #pragma unroll
            for (int mt = 0; mt < 4; mt++) {
                MMA16(acc[mt][0], a[mt], b[0][0], b[0][2]);
                MMA16(acc[mt][1], a[mt], b[0][1], b[0][3]);
                MMA16(acc[mt][2], a[mt], b[1][0], b[1][2]);
                MMA16(acc[mt][3], a[mt], b[1][1], b[1][3]);
            }
        }
    }

    // epilogue: acc + bias -> GMEM
    const float* bias_s = (const float*)smem;
    #pragma unroll
    for (int mt = 0; mt < 4; mt++) {
        #pragma unroll
        for (int nt = 0; nt < 4; nt++) {
            const int bc = wn * 32 + nt * 8 + 2 * tg;
            const int R0 = m0 + wm * 64 + mt * 16 + g;
            float2 v0 = { acc[mt][nt][0] + bias_s[bc], acc[mt][nt][1] + bias_s[bc + 1] };
            float2 v1 = { acc[mt][nt][2] + bias_s[bc], acc[mt][nt][3] + bias_s[bc + 1] };
            *(float2*)(out + (size_t)R0 * NDIM + n0 + bc) = v0;
            *(float2*)(out + (size_t)(R0 + 8) * NDIM + n0 + bc) = v1;
        }
    }
}

extern "C" void kernel_launch(void* const* d_in, const int* in_sizes, int n_in,
                              void* d_out, int out_size) {
    (void)in_sizes; (void)n_in; (void)out_size;
    cudaFuncSetAttribute(vlin_gemm, cudaFuncAttributeMaxDynamicSharedMemorySize, SMEM_TOTAL);

    // inputs: x, weight_mu, weight_sigma, bias_mu, bias_sigma, eps_w, eps_b
    prep_x<<<(MDIM * KDIM / 8) / 256, 256>>>((const float*)d_in[0]);
    prep_w<<<(NDIM * KDIM / 8) / 256, 256>>>((const float*)d_in[1],
                                             (const float*)d_in[2],
                                             (const float*)d_in[5]);
    dim3 grid(MDIM / BM, NDIM / BN);   // (4, 32)
    vlin_gemm<<<grid, THREADS, SMEM_TOTAL>>>(
        (const float*)d_in[3], (const float*)d_in[4], (const float*)d_in[6],
        (float*)d_out);
}